// round 16
// baseline (speedup 1.0000x reference)
#include <cuda_runtime.h>
#include <cstdint>
#include <cstddef>

// Problem dims
#define BB 2
#define MM 4096
#define NN 4096
#define KK 4096
#define KW 128              // 4096 bits = 128 u32 words per row
#define KW_CHUNK 64         // K processed in 2 chunks of 64 words

// Bit-packed signs, TRANSPOSED [b][kw][m]
__device__ __align__(16) uint32_t g_xb[(size_t)BB * KW * MM];   // 4 MB
__device__ __align__(16) uint32_t g_yb[(size_t)BB * KW * NN];   // 4 MB

// ---------------------------------------------------------------------------
// Dual pack (R14-validated): one launch packs BOTH tensors.
// ---------------------------------------------------------------------------
__global__ void pack_bits2(const float* __restrict__ x, const float* __restrict__ y,
                           uint32_t* __restrict__ xb, uint32_t* __restrict__ yb,
                           int nwords) {
    int t = blockIdx.x * blockDim.x + threadIdx.x;
    const float* in;
    uint32_t* out;
    int tt;
    if (t < nwords)      { in = x; out = xb; tt = t; }
    else if (t < 2 * nwords) { in = y; out = yb; tt = t - nwords; }
    else return;

    int m  = tt % MM;
    int kw = (tt / MM) % KW;
    int b  = tt / (MM * KW);

    const float4* p = reinterpret_cast<const float4*>(
        in + ((size_t)b * MM + m) * KK + kw * 32);

    uint32_t w = 0;
    #pragma unroll
    for (int j = 0; j < 8; j++) {
        float4 v = p[j];
        w |= (__float_as_uint(v.x) >> 31) << (j * 4 + 0);
        w |= (__float_as_uint(v.y) >> 31) << (j * 4 + 1);
        w |= (__float_as_uint(v.z) >> 31) << (j * 4 + 2);
        w |= (__float_as_uint(v.w) >> 31) << (j * 4 + 3);
    }
    out[((size_t)b * KW + kw) * MM + m] = w;
}

// ---------------------------------------------------------------------------
// POPC GEMM, single-level 3:2 CSA with parity pre-transform:
//  - smem triple rows (3t+2) overwritten with parity r0^r1^r2 once per chunk
//  - per pair per triple: x0,x1,s = 3 XOR; c = majp (LOP3 0xD4); 2 POPC;
//    w = ps + 2*pc and acc-merge via IMAD (fma pipe).
// CTA tile 128x128, 256 threads, 8x8 outputs/thread, packed 16-bit accs.
// Small operand footprint -> 3 CTAs/SM (24 warps) for latency hiding.
// ---------------------------------------------------------------------------
static constexpr int SMEM_TOTAL = 2 * KW_CHUNK * 128 * 4;   // 65536

__device__ __forceinline__ void cp16(uint32_t dst, const void* src) {
    asm volatile("cp.async.cg.shared.global [%0], [%1], 16;" :: "r"(dst), "l"(src));
}
// maj(a,b,a^b^c) = (a&b)|((a^b)&~s)  -> LOP3 immediate 0xD4
__device__ __forceinline__ uint32_t majp(uint32_t a, uint32_t b, uint32_t s) {
    uint32_t r;
    asm("lop3.b32 %0, %1, %2, %3, 0xD4;" : "=r"(r) : "r"(a), "r"(b), "r"(s));
    return r;
}
__device__ __forceinline__ uint32_t xor3(uint32_t a, uint32_t b, uint32_t c) {
    uint32_t r;
    asm("lop3.b32 %0, %1, %2, %3, 0x96;" : "=r"(r) : "r"(a), "r"(b), "r"(c));
    return r;
}

__global__ void __launch_bounds__(256, 3)
bingemm_popc(const float* __restrict__ xclip, const float* __restrict__ yclip,
             float* __restrict__ out) {
    extern __shared__ __align__(16) uint32_t smem[];
    uint32_t* As = smem;                    // [kw][m]  64 x 128
    uint32_t* Bs = smem + KW_CHUNK * 128;   // [kw][n]  64 x 128
    uint32_t sb;
    asm("{ .reg .u64 t; cvta.to.shared.u64 t, %1; cvt.u32.u64 %0, t; }" : "=r"(sb) : "l"(smem));
    const uint32_t sbB = sb + KW_CHUNK * 128 * 4;

    const int tid = threadIdx.x;
    const int tm8 = tid >> 4;     // 0..15 -> 8 m-rows
    const int tn8 = tid & 15;     // 0..15 -> 8 n-cols
    const int tn = blockIdx.x, tm = blockIdx.y, b = blockIdx.z;

    const uint32_t* Ag = g_xb + (size_t)b * KW * MM + (size_t)tm * 128;
    const uint32_t* Bg = g_yb + (size_t)b * KW * NN + (size_t)tn * 128;

    // Packed accumulators: lo16 = col (tn8*8 + jp), hi16 = col (tn8*8 + 4 + jp)
    uint32_t acc[8][4];
    #pragma unroll
    for (int i = 0; i < 8; i++)
        #pragma unroll
        for (int j = 0; j < 4; j++) acc[i][j] = 0;

    #pragma unroll 1
    for (int ck = 0; ck < KK / (KW_CHUNK * 32); ck++) {     // 2 chunks
        // --- load chunk (R10/R14-identical) ---
        #pragma unroll
        for (int v = 0; v < 8; v++) {
            int idx = tid + v * 256;
            int row = idx >> 5;
            int c4  = (idx & 31) * 4;
            cp16(sb  + (row * 128 + c4) * 4, Ag + (size_t)(ck * KW_CHUNK + row) * MM + c4);
            cp16(sbB + (row * 128 + c4) * 4, Bg + (size_t)(ck * KW_CHUNK + row) * NN + c4);
        }
        asm volatile("cp.async.commit_group;" ::: "memory");
        asm volatile("cp.async.wait_group 0;" ::: "memory");
        __syncthreads();

        // --- parity pre-transform (R15-validated): rows 3t+2 := r0^r1^r2 ---
        #pragma unroll
        for (int k = 0; k < 21; k++) {
            int w   = tid + k * 256;            // 0..5375
            int op  = (w >= 2688) ? 1 : 0;
            int rem = w - op * 2688;
            int t   = rem >> 7;                 // triple 0..20
            int col = rem & 127;
            uint32_t* base = op ? Bs : As;
            uint32_t r0 = base[(3 * t + 0) * 128 + col];
            uint32_t r1 = base[(3 * t + 1) * 128 + col];
            uint32_t r2 = base[(3 * t + 2) * 128 + col];
            base[(3 * t + 2) * 128 + col] = xor3(r0, r1, r2);
        }
        __syncthreads();

        // --- compute: 21 triples + leftover word 63 ---
        #pragma unroll 1
        for (int t = 0; t < 21; t++) {
            const int kw = t * 3;
            uint32_t av[3][8];
            #pragma unroll
            for (int r = 0; r < 3; r++) {
                uint4 t0 = *reinterpret_cast<const uint4*>(&As[(kw + r) * 128 + tm8 * 8]);
                uint4 t1 = *reinterpret_cast<const uint4*>(&As[(kw + r) * 128 + tm8 * 8 + 4]);
                av[r][0] = t0.x; av[r][1] = t0.y; av[r][2] = t0.z; av[r][3] = t0.w;
                av[r][4] = t1.x; av[r][5] = t1.y; av[r][6] = t1.z; av[r][7] = t1.w;
            }
            #pragma unroll
            for (int jb = 0; jb < 2; jb++) {
                uint32_t bv[3][4];
                #pragma unroll
                for (int r = 0; r < 3; r++) {
                    uint4 tt = *reinterpret_cast<const uint4*>(
                        &Bs[(kw + r) * 128 + tn8 * 8 + jb * 4]);
                    bv[r][0] = tt.x; bv[r][1] = tt.y; bv[r][2] = tt.z; bv[r][3] = tt.w;
                }
                #pragma unroll
                for (int ii = 0; ii < 8; ii++) {
                    #pragma unroll
                    for (int jj = 0; jj < 4; jj++) {
                        uint32_t x0 = av[0][ii] ^ bv[0][jj];
                        uint32_t x1 = av[1][ii] ^ bv[1][jj];
                        uint32_t s  = av[2][ii] ^ bv[2][jj];   // parity row
                        uint32_t c  = majp(x0, x1, s);
                        uint32_t w  = __popc(s) + 2u * __popc(c);  // IMAD
                        acc[ii][jj] += (jb ? (w << 16) : w);       // IMAD/IADD
                    }
                }
            }
        }
        // leftover word kw = 63 (untouched by the transform)
        {
            const int kw = 63;
            uint4 a0 = *reinterpret_cast<const uint4*>(&As[kw * 128 + tm8 * 8]);
            uint4 a1 = *reinterpret_cast<const uint4*>(&As[kw * 128 + tm8 * 8 + 4]);
            uint4 b0 = *reinterpret_cast<const uint4*>(&Bs[kw * 128 + tn8 * 8]);
            uint4 b1 = *reinterpret_cast<const uint4*>(&Bs[kw * 128 + tn8 * 8 + 4]);
            uint32_t av[8] = {a0.x, a0.y, a0.z, a0.w, a1.x, a1.y, a1.z, a1.w};
            uint32_t bv[8] = {b0.x, b0.y, b0.z, b0.w, b1.x, b1.y, b1.z, b1.w};
            #pragma unroll
            for (int i = 0; i < 8; i++) {
                #pragma unroll
                for (int jj = 0; jj < 4; jj++) {
                    acc[i][jj] += __popc(av[i] ^ bv[jj]);
                    acc[i][jj] += __popc(av[i] ^ bv[jj + 4]) << 16;
                }
            }
        }
        __syncthreads();   // before next chunk overwrites smem
    }

    // --- epilogue: unpack, dot = KK - 2*cnt, scale, store ---
    const float scale = xclip[0] * yclip[0];
    const int m0 = tm * 128 + tm8 * 8;
    const int n0 = tn * 128 + tn8 * 8;

    #pragma unroll
    for (int i = 0; i < 8; i++) {
        float* orow = out + ((size_t)b * MM + m0 + i) * NN + n0;
        float4 v0, v1;
        v0.x = (float)(KK - 2 * (int)(acc[i][0] & 0xFFFF)) * scale;
        v0.y = (float)(KK - 2 * (int)(acc[i][1] & 0xFFFF)) * scale;
        v0.z = (float)(KK - 2 * (int)(acc[i][2] & 0xFFFF)) * scale;
        v0.w = (float)(KK - 2 * (int)(acc[i][3] & 0xFFFF)) * scale;
        v1.x = (float)(KK - 2 * (int)(acc[i][0] >> 16)) * scale;
        v1.y = (float)(KK - 2 * (int)(acc[i][1] >> 16)) * scale;
        v1.z = (float)(KK - 2 * (int)(acc[i][2] >> 16)) * scale;
        v1.w = (float)(KK - 2 * (int)(acc[i][3] >> 16)) * scale;
        *reinterpret_cast<float4*>(orow)     = v0;
        *reinterpret_cast<float4*>(orow + 4) = v1;
    }
}

// ---------------------------------------------------------------------------
// Launch
// ---------------------------------------------------------------------------
extern "C" void kernel_launch(void* const* d_in, const int* in_sizes, int n_in,
                              void* d_out, int out_size) {
    const float* x     = (const float*)d_in[0];
    const float* y     = (const float*)d_in[1];
    const float* xclip = (const float*)d_in[2];
    const float* yclip = (const float*)d_in[3];
    float* out = (float*)d_out;

    uint32_t *xb, *yb;
    cudaGetSymbolAddress((void**)&xb, g_xb);
    cudaGetSymbolAddress((void**)&yb, g_yb);

    const int nwords = BB * KW * MM;                    // 1,048,576 per tensor
    pack_bits2<<<(2 * nwords + 255) / 256, 256>>>(x, y, xb, yb, nwords);

    cudaFuncSetAttribute(bingemm_popc, cudaFuncAttributeMaxDynamicSharedMemorySize, SMEM_TOTAL);
    dim3 grid(NN / 128, MM / 128, BB);
    bingemm_popc<<<grid, 256, SMEM_TOTAL>>>(xclip, yclip, out);
}